// round 11
// baseline (speedup 1.0000x reference)
#include <cuda_runtime.h>
#include <cuda_bf16.h>
#include <cstdint>

// ---------------------------------------------------------------------------
// GPT-1 forward: B=4, S=1024, D=768, H=12, HD=64, N_LAYER=5
// Round 11 (= R10 resubmit after infra failure): gemm3 with 4 warps x 64x64
// tiles (halved LDS duplication); float4 add_ln.
// ---------------------------------------------------------------------------

#define NB 4
#define SS 1024
#define DD 768
#define HH 12
#define HDD 64
#define NLAYER 5
#define TOKENS (NB * SS)           // 4096
#define D3 (3 * DD)                // 2304
#define D4 (4 * DD)                // 3072

// -------------------- device scratch (no cudaMalloc allowed) ---------------
__device__ __align__(128) float g_h[TOKENS * DD];
__device__ __align__(128) float g_hr[TOKENS * DD];
__device__ __align__(128) float g_n[TOKENS * DD];
__device__ __align__(128) float g_nr[TOKENS * DD];
__device__ __align__(128) float g_tmp[TOKENS * DD];
__device__ __align__(128) float g_attn[TOKENS * DD];
__device__ __align__(128) float g_qkv[TOKENS * D3];
__device__ __align__(128) float g_fc[TOKENS * D4];
__device__ __align__(128) float g_wta[NLAYER * DD * D3];
__device__ __align__(128) float g_wtp[NLAYER * DD * DD];
__device__ __align__(128) float g_wtf[NLAYER * DD * D4];
__device__ __align__(128) float g_wtm[NLAYER * D4 * DD];
__device__ int g_is_i64;

// -------------------- helpers ----------------------------------------------
__device__ __forceinline__ float warp_sum(float v) {
    #pragma unroll
    for (int o = 16; o; o >>= 1) v += __shfl_xor_sync(0xffffffffu, v, o);
    return v;
}
__device__ __forceinline__ float gelu_f(float x) {
    const float c2 = 1.5957691216057308f;  // 2*sqrt(2/pi)
    float u = c2 * (x + 0.044715f * x * x * x);
    return x / (1.0f + __expf(-u));
}
__device__ __forceinline__ uint32_t to_tf32(float x) {
    uint32_t u;
    asm("cvt.rna.tf32.f32 %0, %1;" : "=r"(u) : "f"(x));
    return u;
}
__device__ __forceinline__ float to_tf32f(float x) {
    return __uint_as_float(to_tf32(x));
}
__device__ __forceinline__ void mma8(float* c, const uint32_t* a, const uint32_t* b) {
    asm volatile(
        "mma.sync.aligned.m16n8k8.row.col.f32.tf32.tf32.f32 "
        "{%0,%1,%2,%3},{%4,%5,%6,%7},{%8,%9},{%0,%1,%2,%3};\n"
        : "+f"(c[0]), "+f"(c[1]), "+f"(c[2]), "+f"(c[3])
        : "r"(a[0]), "r"(a[1]), "r"(a[2]), "r"(a[3]), "r"(b[0]), "r"(b[1]));
}
__device__ __forceinline__ void ldsm4(uint32_t* r, uint32_t addr) {
    asm volatile("ldmatrix.sync.aligned.m8n8.x4.shared.b16 {%0,%1,%2,%3}, [%4];"
                 : "=r"(r[0]), "=r"(r[1]), "=r"(r[2]), "=r"(r[3]) : "r"(addr));
}
__device__ __forceinline__ void cpasync16(uint32_t dst, const float* src) {
    asm volatile("cp.async.cg.shared.global [%0], [%1], 16;" :: "r"(dst), "l"(src));
}

// -------------------- input_ids dtype detection ----------------------------
__global__ void detect_kernel(const int* __restrict__ ids) {
    int any = 0;
    for (int i = 1; i < 64; i += 2) any |= ids[i];
    g_is_i64 = (any == 0) ? 1 : 0;
}

// -------------------- embedding (dual write: fp32 + tf32-rounded) ----------
__global__ void embed_kernel(const int* __restrict__ ids,
                             const float* __restrict__ tok,
                             const float* __restrict__ pos,
                             float* __restrict__ h,
                             float* __restrict__ hr) {
    int i = blockIdx.x * blockDim.x + threadIdx.x;
    if (i >= TOKENS * DD) return;
    int t = i / DD;
    int d = i - t * DD;
    int s = t & (SS - 1);
    int id = g_is_i64 ? ids[2 * t] : ids[t];
    float v = tok[(size_t)id * DD + d] + pos[(size_t)s * DD + d];
    h[i] = v;
    hr[i] = to_tf32f(v);
}

// -------------------- all weight transposes in ONE launch -------------------
#define TA_TILES (NLAYER * (D3 / 32) * (DD / 32))
#define TP_TILES (NLAYER * (DD / 32) * (DD / 32))
#define TF_TILES (NLAYER * (D4 / 32) * (DD / 32))
#define TM_TILES (NLAYER * (DD / 32) * (D4 / 32))
#define T_TOTAL  (TA_TILES + TP_TILES + TF_TILES + TM_TILES)

__global__ void transpose_all(const float* __restrict__ wa, float* __restrict__ ta,
                              const float* __restrict__ wp, float* __restrict__ tp,
                              const float* __restrict__ wf, float* __restrict__ tf,
                              const float* __restrict__ wm, float* __restrict__ tm) {
    __shared__ float t[32][33];
    int bid = blockIdx.x;
    const float* src; float* dst; int K, N;
    if (bid < TA_TILES)            { src = wa; dst = ta; K = DD; N = D3; }
    else if (bid < TA_TILES + TP_TILES) {
        bid -= TA_TILES;            src = wp; dst = tp; K = DD; N = DD; }
    else if (bid < TA_TILES + TP_TILES + TF_TILES) {
        bid -= TA_TILES + TP_TILES; src = wf; dst = tf; K = DD; N = D4; }
    else {
        bid -= TA_TILES + TP_TILES + TF_TILES;
                                    src = wm; dst = tm; K = D4; N = DD; }
    int ntx = N / 32;
    int per = ntx * (K / 32);
    int layer = bid / per;
    int tt = bid - layer * per;
    int n0 = (tt % ntx) * 32;
    int k0 = (tt / ntx) * 32;
    size_t off = (size_t)layer * K * N;

    int tx = threadIdx.x, ty = threadIdx.y;
    #pragma unroll
    for (int i = 0; i < 4; i++)
        t[ty + i * 8][tx] = src[off + (size_t)(k0 + ty + i * 8) * N + n0 + tx];
    __syncthreads();
    #pragma unroll
    for (int i = 0; i < 4; i++)
        dst[off + (size_t)(n0 + ty + i * 8) * K + k0 + tx] =
            to_tf32f(t[tx][ty + i * 8]);
}

// ---------------------------------------------------------------------------
// cp.async 3-stage tf32 GEMM, BK=32, 128 threads = 4 warps of 64x64.
// A [M][K], Bt [N][K] (both pre-rounded). ldmatrix frags from [r][36] smem.
// MODE 0: +bias.  MODE 1: rna(gelu(+bias)).  MODE 2: rna(+bias).
// ---------------------------------------------------------------------------
template<int MODE>
__global__ __launch_bounds__(128, 2)
void gemm3(const float* __restrict__ A,
           const float* __restrict__ Bt,
           const float* __restrict__ bias,
           float* __restrict__ C, int ldc,
           int K) {
    constexpr int BM = 128, BK = 32;
    constexpr int RS = BK + 4;               // 36-word row stride
    constexpr int SW = BM * RS;              // words per operand stage

    extern __shared__ float dyn[];
    float* AsBase = dyn;                      // 3 stages A
    float* BsBase = dyn + 3 * SW;             // 3 stages B

    const int tid  = threadIdx.x;
    const int wid  = tid >> 5;
    const int lane = tid & 31;
    const int g    = lane >> 2;
    const int tg   = lane & 3;
    const int warpM = (wid >> 1) * 64;
    const int warpN = (wid & 1) * 64;
    const int rowBase = blockIdx.y * BM;
    const int colBase = blockIdx.x * BM;

    const uint32_t aSm = (uint32_t)__cvta_generic_to_shared(AsBase);
    const uint32_t bSm = (uint32_t)__cvta_generic_to_shared(BsBase);
    const uint32_t aLaneOff = ((lane & 15) * RS + ((lane & 16) ? 4 : 0)) * 4;
    const uint32_t bLaneOff = ((((lane & 7) | ((lane & 16) >> 1))) * RS +
                               ((lane & 8) ? 4 : 0)) * 4;

    const int r  = tid >> 3;        // 0..15 (+16.. for later batches)
    const int kq = tid & 7;

    float acc[4][8][4];
    #pragma unroll
    for (int i = 0; i < 4; i++)
        #pragma unroll
        for (int j = 0; j < 8; j++)
            #pragma unroll
            for (int q = 0; q < 4; q++) acc[i][j][q] = 0.0f;

    auto stage = [&](int kt, int buf) {
        int k0 = kt * BK;
        uint32_t aB = aSm + buf * SW * 4;
        uint32_t bB = bSm + buf * SW * 4;
        #pragma unroll
        for (int it = 0; it < 8; it++) {
            int rr = r + it * 16;
            cpasync16(aB + (rr * RS + kq * 4) * 4,
                      A + (size_t)(rowBase + rr) * K + k0 + kq * 4);
        }
        #pragma unroll
        for (int it = 0; it < 8; it++) {
            int nn = r + it * 16;
            cpasync16(bB + (nn * RS + kq * 4) * 4,
                      Bt + (size_t)(colBase + nn) * K + k0 + kq * 4);
        }
        asm volatile("cp.async.commit_group;");
    };

    const int KT = K / BK;
    stage(0, 0);
    stage(1, 1);

    for (int kt = 0; kt < KT; kt++) {
        if (kt == KT - 1)
            asm volatile("cp.async.wait_group 0;");
        else
            asm volatile("cp.async.wait_group 1;");
        __syncthreads();
        if (kt + 2 < KT) stage(kt + 2, (kt + 2) % 3);

        int buf = kt % 3;
        uint32_t aBase = aSm + buf * SW * 4 + aLaneOff + (warpM * RS) * 4;
        uint32_t bBase = bSm + buf * SW * 4 + bLaneOff + (warpN * RS) * 4;
        #pragma unroll
        for (int kk = 0; kk < BK; kk += 8) {
            uint32_t af[4][4];
            #pragma unroll
            for (int i = 0; i < 4; i++)
                ldsm4(af[i], aBase + kk * 4 + i * (16 * RS * 4));
            uint32_t bf[8][2];
            #pragma unroll
            for (int m = 0; m < 4; m++) {
                uint32_t t4[4];
                ldsm4(t4, bBase + kk * 4 + m * (16 * RS * 4));
                bf[2 * m][0] = t4[0];     bf[2 * m][1] = t4[1];
                bf[2 * m + 1][0] = t4[2]; bf[2 * m + 1][1] = t4[3];
            }
            #pragma unroll
            for (int i = 0; i < 4; i++)
                #pragma unroll
                for (int j = 0; j < 8; j++)
                    mma8(acc[i][j], af[i], bf[j]);
        }
    }

    #pragma unroll
    for (int i = 0; i < 4; i++) {
        int r0 = rowBase + warpM + i * 16 + g;
        int r1 = r0 + 8;
        #pragma unroll
        for (int j = 0; j < 8; j++) {
            int c = colBase + warpN + j * 8 + tg * 2;
            float bb0 = bias[c], bb1 = bias[c + 1];
            float v0 = acc[i][j][0] + bb0, v1 = acc[i][j][1] + bb1;
            float v2 = acc[i][j][2] + bb0, v3 = acc[i][j][3] + bb1;
            if (MODE == 1) {
                v0 = to_tf32f(gelu_f(v0)); v1 = to_tf32f(gelu_f(v1));
                v2 = to_tf32f(gelu_f(v2)); v3 = to_tf32f(gelu_f(v3));
            }
            if (MODE == 2) {
                v0 = to_tf32f(v0); v1 = to_tf32f(v1);
                v2 = to_tf32f(v2); v3 = to_tf32f(v3);
            }
            *reinterpret_cast<float2*>(C + (size_t)r0 * ldc + c) = make_float2(v0, v1);
            *reinterpret_cast<float2*>(C + (size_t)r1 * ldc + c) = make_float2(v2, v3);
        }
    }
}

// ---------------------------------------------------------------------------
// Fused flash attention: 128 q-rows/CTA, 8 warps (16 rows each).
// Inputs (qkv) pre-rounded by QKV GEMM epilogue.  K/V double-buffered via
// cp.async.  q-tiles processed in reverse block order (heavy first).
// ---------------------------------------------------------------------------
#define FS 68

__global__ __launch_bounds__(256)
void flash_kernel(const float* __restrict__ qkv,
                  const float* __restrict__ mask,
                  float* __restrict__ attn) {
    extern __shared__ float sm[];
    float* Qs  = sm;                      // [128 m][68 d]
    float* Ks  = Qs + 128 * FS;           // [2][64 t][68 d]
    float* Vs  = Ks + 2 * 64 * FS;        // [2][64 t][68 d]
    float* Ems = Vs + 2 * 64 * FS;        // [1024]

    const int tid  = threadIdx.x;
    const int wid  = tid >> 5;
    const int lane = tid & 31;
    const int g    = lane >> 2;
    const int tg   = lane & 3;
    const int qi = gridDim.x - 1 - blockIdx.x;   // heavy tiles first
    const int qBase = qi * 128;
    const int bh = blockIdx.y;
    const int b = bh / HH, h = bh - b * HH;

    const float* Qg = qkv + (size_t)b * SS * D3 + h * HDD;
    const float* Kg = Qg + DD;
    const float* Vg = Qg + 2 * DD;

    const uint32_t qSm = (uint32_t)__cvta_generic_to_shared(Qs);
    const uint32_t kSm = (uint32_t)__cvta_generic_to_shared(Ks);
    const uint32_t vSm = (uint32_t)__cvta_generic_to_shared(Vs);

    #pragma unroll
    for (int i = 0; i < 8; i++) {
        int idx = i * 256 + tid;
        int r = idx >> 4, dq = idx & 15;
        cpasync16(qSm + (r * FS + dq * 4) * 4,
                  Qg + (size_t)(qBase + r) * D3 + dq * 4);
    }
    auto stageKV = [&](int kb, int buf) {
        uint32_t kD = kSm + buf * 64 * FS * 4;
        uint32_t vD = vSm + buf * 64 * FS * 4;
        const float* Kt = Kg + (size_t)(kb * 64) * D3;
        const float* Vt = Vg + (size_t)(kb * 64) * D3;
        #pragma unroll
        for (int i = 0; i < 4; i++) {
            int idx = i * 256 + tid;
            int kt = idx >> 4, dq = idx & 15;
            cpasync16(kD + (kt * FS + dq * 4) * 4, Kt + (size_t)kt * D3 + dq * 4);
            cpasync16(vD + (kt * FS + dq * 4) * 4, Vt + (size_t)kt * D3 + dq * 4);
        }
        asm volatile("cp.async.commit_group;");
    };
    stageKV(0, 0);

    #pragma unroll
    for (int i = 0; i < 4; i++) {
        int idx = i * 256 + tid;
        Ems[idx] = (1.0f - mask[b * SS + idx]) * (-3.402823466e38f);
    }

    float o[8][4];
    #pragma unroll
    for (int j = 0; j < 8; j++)
        #pragma unroll
        for (int q = 0; q < 4; q++) o[j][q] = 0.0f;
    float mrow0 = -1e30f, mrow1 = -1e30f;
    float lrow0 = 0.f, lrow1 = 0.f;

    const int row0 = qBase + wid * 16 + g;
    const int row1 = row0 + 8;
    const int srcA = (lane & 28) | (tg >> 1);
    const int srcB = srcA | 2;
    const int e1   = tg & 1;

    const uint32_t aOff = ((wid * 16 + (lane & 15)) * FS + ((lane & 16) ? 4 : 0)) * 4;
    const uint32_t bOff = ((((lane & 7) | ((lane & 16) >> 1))) * FS +
                           ((lane & 8) ? 4 : 0)) * 4;

    const int nkb = qi * 2 + 2;
    for (int kb = 0; kb < nkb; kb++) {
        asm volatile("cp.async.wait_group 0;");
        __syncthreads();
        if (kb + 1 < nkb) stageKV(kb + 1, (kb + 1) & 1);

        const uint32_t kBuf = kSm + (kb & 1) * 64 * FS * 4;
        const float*  VsB  = Vs + (kb & 1) * 64 * FS;

        float s[8][4];
        #pragma unroll
        for (int j = 0; j < 8; j++)
            #pragma unroll
            for (int q = 0; q < 4; q++) s[j][q] = 0.0f;

        #pragma unroll
        for (int kk = 0; kk < 8; kk++) {
            uint32_t af[4];
            ldsm4(af, qSm + aOff + kk * 8 * 4);
            uint32_t bf[8][2];
            #pragma unroll
            for (int m = 0; m < 4; m++) {
                uint32_t t4[4];
                ldsm4(t4, kBuf + bOff + (m * 16 * FS + kk * 8) * 4);
                bf[2 * m][0] = t4[0]; bf[2 * m][1] = t4[1];
                bf[2 * m + 1][0] = t4[2]; bf[2 * m + 1][1] = t4[3];
            }
            #pragma unroll
            for (int j = 0; j < 8; j++)
                mma8(s[j], af, bf[j]);
        }

        float mx0 = -1e30f, mx1 = -1e30f;
        #pragma unroll
        for (int j = 0; j < 8; j++) {
            int c0 = kb * 64 + j * 8 + tg * 2;
            float em0 = Ems[c0];
            float em1 = Ems[c0 + 1];
            float v0 = s[j][0] * 0.125f;
            float v1 = s[j][1] * 0.125f;
            float v2 = s[j][2] * 0.125f;
            float v3 = s[j][3] * 0.125f;
            if (c0 > row0)     v0 = -1e4f;
            if (c0 + 1 > row0) v1 = -1e4f;
            if (c0 > row1)     v2 = -1e4f;
            if (c0 + 1 > row1) v3 = -1e4f;
            v0 += em0; v1 += em1; v2 += em0; v3 += em1;
            s[j][0] = v0; s[j][1] = v1; s[j][2] = v2; s[j][3] = v3;
            mx0 = fmaxf(mx0, fmaxf(v0, v1));
            mx1 = fmaxf(mx1, fmaxf(v2, v3));
        }
        mx0 = fmaxf(mx0, __shfl_xor_sync(0xffffffffu, mx0, 1));
        mx0 = fmaxf(mx0, __shfl_xor_sync(0xffffffffu, mx0, 2));
        mx1 = fmaxf(mx1, __shfl_xor_sync(0xffffffffu, mx1, 1));
        mx1 = fmaxf(mx1, __shfl_xor_sync(0xffffffffu, mx1, 2));

        float mn0 = fmaxf(mrow0, mx0);
        float mn1 = fmaxf(mrow1, mx1);
        float al0 = __expf(mrow0 - mn0);
        float al1 = __expf(mrow1 - mn1);
        mrow0 = mn0; mrow1 = mn1;

        float sum0 = 0.f, sum1 = 0.f;
        #pragma unroll
        for (int j = 0; j < 8; j++) {
            float p0 = __expf(s[j][0] - mn0);
            float p1 = __expf(s[j][1] - mn0);
            float p2 = __expf(s[j][2] - mn1);
            float p3 = __expf(s[j][3] - mn1);
            s[j][0] = p0; s[j][1] = p1; s[j][2] = p2; s[j][3] = p3;
            sum0 += p0 + p1; sum1 += p2 + p3;
        }
        sum0 += __shfl_xor_sync(0xffffffffu, sum0, 1);
        sum0 += __shfl_xor_sync(0xffffffffu, sum0, 2);
        sum1 += __shfl_xor_sync(0xffffffffu, sum1, 1);
        sum1 += __shfl_xor_sync(0xffffffffu, sum1, 2);
        lrow0 = lrow0 * al0 + sum0;
        lrow1 = lrow1 * al1 + sum1;

        #pragma unroll
        for (int jo = 0; jo < 8; jo++) {
            o[jo][0] *= al0; o[jo][1] *= al0;
            o[jo][2] *= al1; o[jo][3] *= al1;
        }

        #pragma unroll
        for (int j = 0; j < 8; j++) {
            float x0A = __shfl_sync(0xffffffffu, s[j][0], srcA);
            float x1A = __shfl_sync(0xffffffffu, s[j][1], srcA);
            float x0B = __shfl_sync(0xffffffffu, s[j][0], srcB);
            float x1B = __shfl_sync(0xffffffffu, s[j][1], srcB);
            float y0A = __shfl_sync(0xffffffffu, s[j][2], srcA);
            float y1A = __shfl_sync(0xffffffffu, s[j][3], srcA);
            float y0B = __shfl_sync(0xffffffffu, s[j][2], srcB);
            float y1B = __shfl_sync(0xffffffffu, s[j][3], srcB);
            uint32_t pa[4];
            pa[0] = to_tf32(e1 ? x1A : x0A);
            pa[1] = to_tf32(e1 ? y1A : y0A);
            pa[2] = to_tf32(e1 ? x1B : x0B);
            pa[3] = to_tf32(e1 ? y1B : y0B);
            #pragma unroll
            for (int jo = 0; jo < 8; jo++) {
                uint32_t bf[2];
                bf[0] = __float_as_uint(VsB[(j * 8 + tg) * FS + jo * 8 + g]);
                bf[1] = __float_as_uint(VsB[(j * 8 + tg + 4) * FS + jo * 8 + g]);
                mma8(o[jo], pa, bf);
            }
        }
    }

    float inv0 = 1.0f / lrow0;
    float inv1 = 1.0f / lrow1;
    #pragma unroll
    for (int jo = 0; jo < 8; jo++) {
        int col = h * HDD + jo * 8 + tg * 2;
        *reinterpret_cast<float2*>(attn + (size_t)(b * SS + row0) * DD + col) =
            make_float2(to_tf32f(o[jo][0] * inv0), to_tf32f(o[jo][1] * inv0));
        *reinterpret_cast<float2*>(attn + (size_t)(b * SS + row1) * DD + col) =
            make_float2(to_tf32f(o[jo][2] * inv1), to_tf32f(o[jo][3] * inv1));
    }
}

// -------------------- fused residual-add + LayerNorm (float4, dual write) --
__global__ __launch_bounds__(192)
void add_ln_kernel(const float* __restrict__ x,
                   const float* __restrict__ y,
                   const float* __restrict__ w,
                   const float* __restrict__ b,
                   float* __restrict__ out,
                   float* __restrict__ out_r) {
    int row = blockIdx.x;
    int tid = threadIdx.x;   // 0..191, one float4 each (192*4 = 768)
    const float4 xv = *reinterpret_cast<const float4*>(x + (size_t)row * DD + tid * 4);
    const float4 yv = *reinterpret_cast<const float4*>(y + (size_t)row * DD + tid * 4);
    float v0 = xv.x + yv.x, v1 = xv.y + yv.y, v2 = xv.z + yv.z, v3 = xv.w + yv.w;

    __shared__ float sh[6];
    float s = warp_sum(v0 + v1 + v2 + v3);
    if ((tid & 31) == 0) sh[tid >> 5] = s;
    __syncthreads();
    float tot = 0.f;
    #pragma unroll
    for (int i = 0; i < 6; i++) tot += sh[i];
    float mu = tot * (1.0f / DD);
    __syncthreads();

    float d0 = v0 - mu, d1 = v1 - mu, d2 = v2 - mu, d3 = v3 - mu;
    float s2 = warp_sum(d0 * d0 + d1 * d1 + d2 * d2 + d3 * d3);
    if ((tid & 31) == 0) sh[tid >> 5] = s2;
    __syncthreads();
    float tot2 = 0.f;
    #pragma unroll
    for (int i = 0; i < 6; i++) tot2 += sh[i];
    float r = rsqrtf(tot2 * (1.0f / DD) + 1e-5f);

    const float4 wv = *reinterpret_cast<const float4*>(w + tid * 4);
    const float4 bv = *reinterpret_cast<const float4*>(b + tid * 4);
    float o0 = d0 * r * wv.x + bv.x;
    float o1 = d1 * r * wv.y + bv.y;
    float o2 = d2 * r * wv.z + bv.z;
    float o3 = d3 * r * wv.w + bv.w;
    *reinterpret_cast<float4*>(out + (size_t)row * DD + tid * 4) =
        make_float4(o0, o1, o2, o3);
    if (out_r) {
        *reinterpret_cast<float4*>(out_r + (size_t)row * DD + tid * 4) =
            make_float4(to_tf32f(o0), to_tf32f(o1), to_tf32f(o2), to_tf32f(o3));
    }
}

// ---------------------------------------------------------------------------
extern "C" void kernel_launch(void* const* d_in, const int* in_sizes, int n_in,
                              void* d_out, int out_size) {
    const int*   ids      = (const int*)  d_in[0];
    const float* mask     = (const float*)d_in[2];
    const float* tok_emb  = (const float*)d_in[3];
    const float* pos_emb  = (const float*)d_in[4];
    const float* c_attn_w = (const float*)d_in[5];
    const float* c_attn_b = (const float*)d_in[6];
    const float* c_proj_w = (const float*)d_in[7];
    const float* c_proj_b = (const float*)d_in[8];
    const float* ln1_w    = (const float*)d_in[9];
    const float* ln1_b    = (const float*)d_in[10];
    const float* c_fc_w   = (const float*)d_in[11];
    const float* c_fc_b   = (const float*)d_in[12];
    const float* mlp_w    = (const float*)d_in[13];
    const float* mlp_b    = (const float*)d_in[14];
    const float* ln2_w    = (const float*)d_in[15];
    const float* ln2_b    = (const float*)d_in[16];

    float *h, *hr, *n, *nr, *tmp, *attn, *qkv, *fc;
    float *wta, *wtp, *wtf, *wtm;
    cudaGetSymbolAddress((void**)&h,    g_h);
    cudaGetSymbolAddress((void**)&hr,   g_hr);
    cudaGetSymbolAddress((void**)&n,    g_n);
    cudaGetSymbolAddress((void**)&nr,   g_nr);
    cudaGetSymbolAddress((void**)&tmp,  g_tmp);
    cudaGetSymbolAddress((void**)&attn, g_attn);
    cudaGetSymbolAddress((void**)&qkv,  g_qkv);
    cudaGetSymbolAddress((void**)&fc,   g_fc);
    cudaGetSymbolAddress((void**)&wta,  g_wta);
    cudaGetSymbolAddress((void**)&wtp,  g_wtp);
    cudaGetSymbolAddress((void**)&wtf,  g_wtf);
    cudaGetSymbolAddress((void**)&wtm,  g_wtm);

    const int gemmSmem  = 3 * 2 * 128 * 36 * 4;                        // 110592 B
    const int flashSmem = (128 * FS + 4 * 64 * FS + 1024) * 4;         // 108544 B
    static int s_attr_set = 0;
    if (!s_attr_set) {
        cudaFuncSetAttribute(gemm3<0>, cudaFuncAttributeMaxDynamicSharedMemorySize, gemmSmem);
        cudaFuncSetAttribute(gemm3<1>, cudaFuncAttributeMaxDynamicSharedMemorySize, gemmSmem);
        cudaFuncSetAttribute(gemm3<2>, cudaFuncAttributeMaxDynamicSharedMemorySize, gemmSmem);
        cudaFuncSetAttribute(flash_kernel, cudaFuncAttributeMaxDynamicSharedMemorySize, flashSmem);
        s_attr_set = 1;
    }

    detect_kernel<<<1, 1>>>(ids);
    embed_kernel<<<(TOKENS * DD + 255) / 256, 256>>>(ids, tok_emb, pos_emb, h, hr);

    transpose_all<<<T_TOTAL, dim3(32, 8)>>>(c_attn_w, wta, c_proj_w, wtp,
                                            c_fc_w, wtf, mlp_w, wtm);

    for (int i = 0; i < NLAYER; i++) {
        // QKV: hr [4096,768] @ Wt [2304,768]^T  (output tf32-rounded for flash)
        gemm3<2><<<dim3(D3 / 128, TOKENS / 128), 128, gemmSmem>>>(
            hr, wta + (size_t)i * DD * D3, c_attn_b + (size_t)i * D3,
            qkv, D3, DD);

        // fused flash attention -> attn (tf32-rounded)
        flash_kernel<<<dim3(SS / 128, NB * HH), 256, flashSmem>>>(qkv, mask, attn);

        // attn out projection
        gemm3<0><<<dim3(DD / 128, TOKENS / 128), 128, gemmSmem>>>(
            attn, wtp + (size_t)i * DD * DD, c_proj_b + (size_t)i * DD,
            tmp, DD, DD);

        // n = LN(h + attn_proj), nr = rna(n)
        add_ln_kernel<<<TOKENS, 192>>>(h, tmp, ln1_w + i * DD, ln1_b + i * DD, n, nr);

        // fc = rna(gelu(nr @ Wfc + b))
        gemm3<1><<<dim3(D4 / 128, TOKENS / 128), 128, gemmSmem>>>(
            nr, wtf + (size_t)i * DD * D4, c_fc_b + (size_t)i * D4,
            fc, D4, DD);

        // m = fc @ Wmlp + b
        gemm3<0><<<dim3(DD / 128, TOKENS / 128), 128, gemmSmem>>>(
            fc, wtm + (size_t)i * D4 * DD, mlp_b + (size_t)i * DD,
            tmp, DD, D4);

        // h = LN(n + m); last layer -> d_out, no rounded copy
        float* dst = (i == NLAYER - 1) ? (float*)d_out : h;
        float* dstr = (i == NLAYER - 1) ? nullptr : hr;
        add_ln_kernel<<<TOKENS, 192>>>(n, tmp, ln2_w + i * DD, ln2_b + i * DD, dst, dstr);
    }
}

// round 12
// speedup vs baseline: 1.0307x; 1.0307x over previous
#include <cuda_runtime.h>
#include <cuda_bf16.h>
#include <cstdint>

// ---------------------------------------------------------------------------
// GPT-1 forward: B=4, S=1024, D=768, H=12, HD=64, N_LAYER=5
// Round 12: gemm3 reverted to R9's proven 256-thread 2x4 shape;
// float4 add_ln retained from R11.
// ---------------------------------------------------------------------------

#define NB 4
#define SS 1024
#define DD 768
#define HH 12
#define HDD 64
#define NLAYER 5
#define TOKENS (NB * SS)           // 4096
#define D3 (3 * DD)                // 2304
#define D4 (4 * DD)                // 3072

// -------------------- device scratch (no cudaMalloc allowed) ---------------
__device__ __align__(128) float g_h[TOKENS * DD];
__device__ __align__(128) float g_hr[TOKENS * DD];
__device__ __align__(128) float g_n[TOKENS * DD];
__device__ __align__(128) float g_nr[TOKENS * DD];
__device__ __align__(128) float g_tmp[TOKENS * DD];
__device__ __align__(128) float g_attn[TOKENS * DD];
__device__ __align__(128) float g_qkv[TOKENS * D3];
__device__ __align__(128) float g_fc[TOKENS * D4];
__device__ __align__(128) float g_wta[NLAYER * DD * D3];
__device__ __align__(128) float g_wtp[NLAYER * DD * DD];
__device__ __align__(128) float g_wtf[NLAYER * DD * D4];
__device__ __align__(128) float g_wtm[NLAYER * D4 * DD];
__device__ int g_is_i64;

// -------------------- helpers ----------------------------------------------
__device__ __forceinline__ float warp_sum(float v) {
    #pragma unroll
    for (int o = 16; o; o >>= 1) v += __shfl_xor_sync(0xffffffffu, v, o);
    return v;
}
__device__ __forceinline__ float gelu_f(float x) {
    const float c2 = 1.5957691216057308f;  // 2*sqrt(2/pi)
    float u = c2 * (x + 0.044715f * x * x * x);
    return x / (1.0f + __expf(-u));
}
__device__ __forceinline__ uint32_t to_tf32(float x) {
    uint32_t u;
    asm("cvt.rna.tf32.f32 %0, %1;" : "=r"(u) : "f"(x));
    return u;
}
__device__ __forceinline__ float to_tf32f(float x) {
    return __uint_as_float(to_tf32(x));
}
__device__ __forceinline__ void mma8(float* c, const uint32_t* a, const uint32_t* b) {
    asm volatile(
        "mma.sync.aligned.m16n8k8.row.col.f32.tf32.tf32.f32 "
        "{%0,%1,%2,%3},{%4,%5,%6,%7},{%8,%9},{%0,%1,%2,%3};\n"
        : "+f"(c[0]), "+f"(c[1]), "+f"(c[2]), "+f"(c[3])
        : "r"(a[0]), "r"(a[1]), "r"(a[2]), "r"(a[3]), "r"(b[0]), "r"(b[1]));
}
__device__ __forceinline__ void ldsm4(uint32_t* r, uint32_t addr) {
    asm volatile("ldmatrix.sync.aligned.m8n8.x4.shared.b16 {%0,%1,%2,%3}, [%4];"
                 : "=r"(r[0]), "=r"(r[1]), "=r"(r[2]), "=r"(r[3]) : "r"(addr));
}
__device__ __forceinline__ void cpasync16(uint32_t dst, const float* src) {
    asm volatile("cp.async.cg.shared.global [%0], [%1], 16;" :: "r"(dst), "l"(src));
}

// -------------------- input_ids dtype detection ----------------------------
__global__ void detect_kernel(const int* __restrict__ ids) {
    int any = 0;
    for (int i = 1; i < 64; i += 2) any |= ids[i];
    g_is_i64 = (any == 0) ? 1 : 0;
}

// -------------------- embedding (dual write: fp32 + tf32-rounded) ----------
__global__ void embed_kernel(const int* __restrict__ ids,
                             const float* __restrict__ tok,
                             const float* __restrict__ pos,
                             float* __restrict__ h,
                             float* __restrict__ hr) {
    int i = blockIdx.x * blockDim.x + threadIdx.x;
    if (i >= TOKENS * DD) return;
    int t = i / DD;
    int d = i - t * DD;
    int s = t & (SS - 1);
    int id = g_is_i64 ? ids[2 * t] : ids[t];
    float v = tok[(size_t)id * DD + d] + pos[(size_t)s * DD + d];
    h[i] = v;
    hr[i] = to_tf32f(v);
}

// -------------------- all weight transposes in ONE launch -------------------
#define TA_TILES (NLAYER * (D3 / 32) * (DD / 32))
#define TP_TILES (NLAYER * (DD / 32) * (DD / 32))
#define TF_TILES (NLAYER * (D4 / 32) * (DD / 32))
#define TM_TILES (NLAYER * (DD / 32) * (D4 / 32))
#define T_TOTAL  (TA_TILES + TP_TILES + TF_TILES + TM_TILES)

__global__ void transpose_all(const float* __restrict__ wa, float* __restrict__ ta,
                              const float* __restrict__ wp, float* __restrict__ tp,
                              const float* __restrict__ wf, float* __restrict__ tf,
                              const float* __restrict__ wm, float* __restrict__ tm) {
    __shared__ float t[32][33];
    int bid = blockIdx.x;
    const float* src; float* dst; int K, N;
    if (bid < TA_TILES)            { src = wa; dst = ta; K = DD; N = D3; }
    else if (bid < TA_TILES + TP_TILES) {
        bid -= TA_TILES;            src = wp; dst = tp; K = DD; N = DD; }
    else if (bid < TA_TILES + TP_TILES + TF_TILES) {
        bid -= TA_TILES + TP_TILES; src = wf; dst = tf; K = DD; N = D4; }
    else {
        bid -= TA_TILES + TP_TILES + TF_TILES;
                                    src = wm; dst = tm; K = D4; N = DD; }
    int ntx = N / 32;
    int per = ntx * (K / 32);
    int layer = bid / per;
    int tt = bid - layer * per;
    int n0 = (tt % ntx) * 32;
    int k0 = (tt / ntx) * 32;
    size_t off = (size_t)layer * K * N;

    int tx = threadIdx.x, ty = threadIdx.y;
    #pragma unroll
    for (int i = 0; i < 4; i++)
        t[ty + i * 8][tx] = src[off + (size_t)(k0 + ty + i * 8) * N + n0 + tx];
    __syncthreads();
    #pragma unroll
    for (int i = 0; i < 4; i++)
        dst[off + (size_t)(n0 + ty + i * 8) * K + k0 + tx] =
            to_tf32f(t[tx][ty + i * 8]);
}

// ---------------------------------------------------------------------------
// cp.async 3-stage tf32 GEMM, BK=32, 256 threads = 8 warps of 64x32 (2x4).
// A [M][K], Bt [N][K] (both pre-rounded). ldmatrix frags from [r][36] smem.
// MODE 0: +bias.  MODE 1: rna(gelu(+bias)).  MODE 2: rna(+bias).
// ---------------------------------------------------------------------------
template<int MODE>
__global__ __launch_bounds__(256, 2)
void gemm3(const float* __restrict__ A,
           const float* __restrict__ Bt,
           const float* __restrict__ bias,
           float* __restrict__ C, int ldc,
           int K) {
    constexpr int BM = 128, BK = 32;
    constexpr int RS = BK + 4;               // 36-word row stride
    constexpr int SW = BM * RS;              // words per operand stage

    extern __shared__ float dyn[];
    float* AsBase = dyn;                      // 3 stages A
    float* BsBase = dyn + 3 * SW;             // 3 stages B

    const int tid  = threadIdx.x;
    const int wid  = tid >> 5;
    const int lane = tid & 31;
    const int g    = lane >> 2;
    const int tg   = lane & 3;
    const int warpM = (wid >> 2) * 64;
    const int warpN = (wid & 3) * 32;
    const int rowBase = blockIdx.y * BM;
    const int colBase = blockIdx.x * BM;

    const uint32_t aSm = (uint32_t)__cvta_generic_to_shared(AsBase);
    const uint32_t bSm = (uint32_t)__cvta_generic_to_shared(BsBase);
    const uint32_t aLaneOff = ((lane & 15) * RS + ((lane & 16) ? 4 : 0)) * 4;
    const uint32_t bLaneOff = ((((lane & 7) | ((lane & 16) >> 1))) * RS +
                               ((lane & 8) ? 4 : 0)) * 4;

    const int r  = tid >> 3;        // 0..31 (+32/64/96 for later batches)
    const int kq = tid & 7;

    float acc[4][4][4];
    #pragma unroll
    for (int i = 0; i < 4; i++)
        #pragma unroll
        for (int j = 0; j < 4; j++)
            #pragma unroll
            for (int q = 0; q < 4; q++) acc[i][j][q] = 0.0f;

    auto stage = [&](int kt, int buf) {
        int k0 = kt * BK;
        uint32_t aB = aSm + buf * SW * 4;
        uint32_t bB = bSm + buf * SW * 4;
        #pragma unroll
        for (int it = 0; it < 4; it++) {
            int rr = r + it * 32;
            cpasync16(aB + (rr * RS + kq * 4) * 4,
                      A + (size_t)(rowBase + rr) * K + k0 + kq * 4);
        }
        #pragma unroll
        for (int it = 0; it < 4; it++) {
            int nn = r + it * 32;
            cpasync16(bB + (nn * RS + kq * 4) * 4,
                      Bt + (size_t)(colBase + nn) * K + k0 + kq * 4);
        }
        asm volatile("cp.async.commit_group;");
    };

    const int KT = K / BK;
    stage(0, 0);
    stage(1, 1);

    for (int kt = 0; kt < KT; kt++) {
        if (kt == KT - 1)
            asm volatile("cp.async.wait_group 0;");
        else
            asm volatile("cp.async.wait_group 1;");
        __syncthreads();
        if (kt + 2 < KT) stage(kt + 2, (kt + 2) % 3);

        int buf = kt % 3;
        uint32_t aBase = aSm + buf * SW * 4 + aLaneOff + (warpM * RS) * 4;
        uint32_t bBase = bSm + buf * SW * 4 + bLaneOff + (warpN * RS) * 4;
        #pragma unroll
        for (int kk = 0; kk < BK; kk += 8) {
            uint32_t af[4][4];
            #pragma unroll
            for (int i = 0; i < 4; i++)
                ldsm4(af[i], aBase + kk * 4 + i * (16 * RS * 4));
            uint32_t bf[4][2];
            {
                uint32_t t[4];
                ldsm4(t, bBase + kk * 4);
                bf[0][0] = t[0]; bf[0][1] = t[1];
                bf[1][0] = t[2]; bf[1][1] = t[3];
                ldsm4(t, bBase + kk * 4 + 16 * RS * 4);
                bf[2][0] = t[0]; bf[2][1] = t[1];
                bf[3][0] = t[2]; bf[3][1] = t[3];
            }
            #pragma unroll
            for (int i = 0; i < 4; i++)
                #pragma unroll
                for (int j = 0; j < 4; j++)
                    mma8(acc[i][j], af[i], bf[j]);
        }
    }

    #pragma unroll
    for (int i = 0; i < 4; i++) {
        int r0 = rowBase + warpM + i * 16 + g;
        int r1 = r0 + 8;
        #pragma unroll
        for (int j = 0; j < 4; j++) {
            int c = colBase + warpN + j * 8 + tg * 2;
            float bb0 = bias[c], bb1 = bias[c + 1];
            float v0 = acc[i][j][0] + bb0, v1 = acc[i][j][1] + bb1;
            float v2 = acc[i][j][2] + bb0, v3 = acc[i][j][3] + bb1;
            if (MODE == 1) {
                v0 = to_tf32f(gelu_f(v0)); v1 = to_tf32f(gelu_f(v1));
                v2 = to_tf32f(gelu_f(v2)); v3 = to_tf32f(gelu_f(v3));
            }
            if (MODE == 2) {
                v0 = to_tf32f(v0); v1 = to_tf32f(v1);
                v2 = to_tf32f(v2); v3 = to_tf32f(v3);
            }
            *reinterpret_cast<float2*>(C + (size_t)r0 * ldc + c) = make_float2(v0, v1);
            *reinterpret_cast<float2*>(C + (size_t)r1 * ldc + c) = make_float2(v2, v3);
        }
    }
}

// ---------------------------------------------------------------------------
// Fused flash attention: 128 q-rows/CTA, 8 warps (16 rows each).
// Inputs (qkv) pre-rounded by QKV GEMM epilogue.  K/V double-buffered via
// cp.async.  q-tiles processed in reverse block order (heavy first).
// ---------------------------------------------------------------------------
#define FS 68

__global__ __launch_bounds__(256)
void flash_kernel(const float* __restrict__ qkv,
                  const float* __restrict__ mask,
                  float* __restrict__ attn) {
    extern __shared__ float sm[];
    float* Qs  = sm;                      // [128 m][68 d]
    float* Ks  = Qs + 128 * FS;           // [2][64 t][68 d]
    float* Vs  = Ks + 2 * 64 * FS;        // [2][64 t][68 d]
    float* Ems = Vs + 2 * 64 * FS;        // [1024]

    const int tid  = threadIdx.x;
    const int wid  = tid >> 5;
    const int lane = tid & 31;
    const int g    = lane >> 2;
    const int tg   = lane & 3;
    const int qi = gridDim.x - 1 - blockIdx.x;   // heavy tiles first
    const int qBase = qi * 128;
    const int bh = blockIdx.y;
    const int b = bh / HH, h = bh - b * HH;

    const float* Qg = qkv + (size_t)b * SS * D3 + h * HDD;
    const float* Kg = Qg + DD;
    const float* Vg = Qg + 2 * DD;

    const uint32_t qSm = (uint32_t)__cvta_generic_to_shared(Qs);
    const uint32_t kSm = (uint32_t)__cvta_generic_to_shared(Ks);
    const uint32_t vSm = (uint32_t)__cvta_generic_to_shared(Vs);

    #pragma unroll
    for (int i = 0; i < 8; i++) {
        int idx = i * 256 + tid;
        int r = idx >> 4, dq = idx & 15;
        cpasync16(qSm + (r * FS + dq * 4) * 4,
                  Qg + (size_t)(qBase + r) * D3 + dq * 4);
    }
    auto stageKV = [&](int kb, int buf) {
        uint32_t kD = kSm + buf * 64 * FS * 4;
        uint32_t vD = vSm + buf * 64 * FS * 4;
        const float* Kt = Kg + (size_t)(kb * 64) * D3;
        const float* Vt = Vg + (size_t)(kb * 64) * D3;
        #pragma unroll
        for (int i = 0; i < 4; i++) {
            int idx = i * 256 + tid;
            int kt = idx >> 4, dq = idx & 15;
            cpasync16(kD + (kt * FS + dq * 4) * 4, Kt + (size_t)kt * D3 + dq * 4);
            cpasync16(vD + (kt * FS + dq * 4) * 4, Vt + (size_t)kt * D3 + dq * 4);
        }
        asm volatile("cp.async.commit_group;");
    };
    stageKV(0, 0);

    #pragma unroll
    for (int i = 0; i < 4; i++) {
        int idx = i * 256 + tid;
        Ems[idx] = (1.0f - mask[b * SS + idx]) * (-3.402823466e38f);
    }

    float o[8][4];
    #pragma unroll
    for (int j = 0; j < 8; j++)
        #pragma unroll
        for (int q = 0; q < 4; q++) o[j][q] = 0.0f;
    float mrow0 = -1e30f, mrow1 = -1e30f;
    float lrow0 = 0.f, lrow1 = 0.f;

    const int row0 = qBase + wid * 16 + g;
    const int row1 = row0 + 8;
    const int srcA = (lane & 28) | (tg >> 1);
    const int srcB = srcA | 2;
    const int e1   = tg & 1;

    const uint32_t aOff = ((wid * 16 + (lane & 15)) * FS + ((lane & 16) ? 4 : 0)) * 4;
    const uint32_t bOff = ((((lane & 7) | ((lane & 16) >> 1))) * FS +
                           ((lane & 8) ? 4 : 0)) * 4;

    const int nkb = qi * 2 + 2;
    for (int kb = 0; kb < nkb; kb++) {
        asm volatile("cp.async.wait_group 0;");
        __syncthreads();
        if (kb + 1 < nkb) stageKV(kb + 1, (kb + 1) & 1);

        const uint32_t kBuf = kSm + (kb & 1) * 64 * FS * 4;
        const float*  VsB  = Vs + (kb & 1) * 64 * FS;

        float s[8][4];
        #pragma unroll
        for (int j = 0; j < 8; j++)
            #pragma unroll
            for (int q = 0; q < 4; q++) s[j][q] = 0.0f;

        #pragma unroll
        for (int kk = 0; kk < 8; kk++) {
            uint32_t af[4];
            ldsm4(af, qSm + aOff + kk * 8 * 4);
            uint32_t bf[8][2];
            #pragma unroll
            for (int m = 0; m < 4; m++) {
                uint32_t t4[4];
                ldsm4(t4, kBuf + bOff + (m * 16 * FS + kk * 8) * 4);
                bf[2 * m][0] = t4[0]; bf[2 * m][1] = t4[1];
                bf[2 * m + 1][0] = t4[2]; bf[2 * m + 1][1] = t4[3];
            }
            #pragma unroll
            for (int j = 0; j < 8; j++)
                mma8(s[j], af, bf[j]);
        }

        float mx0 = -1e30f, mx1 = -1e30f;
        #pragma unroll
        for (int j = 0; j < 8; j++) {
            int c0 = kb * 64 + j * 8 + tg * 2;
            float em0 = Ems[c0];
            float em1 = Ems[c0 + 1];
            float v0 = s[j][0] * 0.125f;
            float v1 = s[j][1] * 0.125f;
            float v2 = s[j][2] * 0.125f;
            float v3 = s[j][3] * 0.125f;
            if (c0 > row0)     v0 = -1e4f;
            if (c0 + 1 > row0) v1 = -1e4f;
            if (c0 > row1)     v2 = -1e4f;
            if (c0 + 1 > row1) v3 = -1e4f;
            v0 += em0; v1 += em1; v2 += em0; v3 += em1;
            s[j][0] = v0; s[j][1] = v1; s[j][2] = v2; s[j][3] = v3;
            mx0 = fmaxf(mx0, fmaxf(v0, v1));
            mx1 = fmaxf(mx1, fmaxf(v2, v3));
        }
        mx0 = fmaxf(mx0, __shfl_xor_sync(0xffffffffu, mx0, 1));
        mx0 = fmaxf(mx0, __shfl_xor_sync(0xffffffffu, mx0, 2));
        mx1 = fmaxf(mx1, __shfl_xor_sync(0xffffffffu, mx1, 1));
        mx1 = fmaxf(mx1, __shfl_xor_sync(0xffffffffu, mx1, 2));

        float mn0 = fmaxf(mrow0, mx0);
        float mn1 = fmaxf(mrow1, mx1);
        float al0 = __expf(mrow0 - mn0);
        float al1 = __expf(mrow1 - mn1);
        mrow0 = mn0; mrow1 = mn1;

        float sum0 = 0.f, sum1 = 0.f;
        #pragma unroll
        for (int j = 0; j < 8; j++) {
            float p0 = __expf(s[j][0] - mn0);
            float p1 = __expf(s[j][1] - mn0);
            float p2 = __expf(s[j][2] - mn1);
            float p3 = __expf(s[j][3] - mn1);
            s[j][0] = p0; s[j][1] = p1; s[j][2] = p2; s[j][3] = p3;
            sum0 += p0 + p1; sum1 += p2 + p3;
        }
        sum0 += __shfl_xor_sync(0xffffffffu, sum0, 1);
        sum0 += __shfl_xor_sync(0xffffffffu, sum0, 2);
        sum1 += __shfl_xor_sync(0xffffffffu, sum1, 1);
        sum1 += __shfl_xor_sync(0xffffffffu, sum1, 2);
        lrow0 = lrow0 * al0 + sum0;
        lrow1 = lrow1 * al1 + sum1;

        #pragma unroll
        for (int jo = 0; jo < 8; jo++) {
            o[jo][0] *= al0; o[jo][1] *= al0;
            o[jo][2] *= al1; o[jo][3] *= al1;
        }

        #pragma unroll
        for (int j = 0; j < 8; j++) {
            float x0A = __shfl_sync(0xffffffffu, s[j][0], srcA);
            float x1A = __shfl_sync(0xffffffffu, s[j][1], srcA);
            float x0B = __shfl_sync(0xffffffffu, s[j][0], srcB);
            float x1B = __shfl_sync(0xffffffffu, s[j][1], srcB);
            float y0A = __shfl_sync(0xffffffffu, s[j][2], srcA);
            float y1A = __shfl_sync(0xffffffffu, s[j][3], srcA);
            float y0B = __shfl_sync(0xffffffffu, s[j][2], srcB);
            float y1B = __shfl_sync(0xffffffffu, s[j][3], srcB);
            uint32_t pa[4];
            pa[0] = to_tf32(e1 ? x1A : x0A);
            pa[1] = to_tf32(e1 ? y1A : y0A);
            pa[2] = to_tf32(e1 ? x1B : x0B);
            pa[3] = to_tf32(e1 ? y1B : y0B);
            #pragma unroll
            for (int jo = 0; jo < 8; jo++) {
                uint32_t bf[2];
                bf[0] = __float_as_uint(VsB[(j * 8 + tg) * FS + jo * 8 + g]);
                bf[1] = __float_as_uint(VsB[(j * 8 + tg + 4) * FS + jo * 8 + g]);
                mma8(o[jo], pa, bf);
            }
        }
    }

    float inv0 = 1.0f / lrow0;
    float inv1 = 1.0f / lrow1;
    #pragma unroll
    for (int jo = 0; jo < 8; jo++) {
        int col = h * HDD + jo * 8 + tg * 2;
        *reinterpret_cast<float2*>(attn + (size_t)(b * SS + row0) * DD + col) =
            make_float2(to_tf32f(o[jo][0] * inv0), to_tf32f(o[jo][1] * inv0));
        *reinterpret_cast<float2*>(attn + (size_t)(b * SS + row1) * DD + col) =
            make_float2(to_tf32f(o[jo][2] * inv1), to_tf32f(o[jo][3] * inv1));
    }
}

// -------------------- fused residual-add + LayerNorm (float4, dual write) --
__global__ __launch_bounds__(192)
void add_ln_kernel(const float* __restrict__ x,
                   const float* __restrict__ y,
                   const float* __restrict__ w,
                   const float* __restrict__ b,
                   float* __restrict__ out,
                   float* __restrict__ out_r) {
    int row = blockIdx.x;
    int tid = threadIdx.x;   // 0..191, one float4 each (192*4 = 768)
    const float4 xv = *reinterpret_cast<const float4*>(x + (size_t)row * DD + tid * 4);
    const float4 yv = *reinterpret_cast<const float4*>(y + (size_t)row * DD + tid * 4);
    float v0 = xv.x + yv.x, v1 = xv.y + yv.y, v2 = xv.z + yv.z, v3 = xv.w + yv.w;

    __shared__ float sh[6];
    float s = warp_sum(v0 + v1 + v2 + v3);
    if ((tid & 31) == 0) sh[tid >> 5] = s;
    __syncthreads();
    float tot = 0.f;
    #pragma unroll
    for (int i = 0; i < 6; i++) tot += sh[i];
    float mu = tot * (1.0f / DD);
    __syncthreads();

    float d0 = v0 - mu, d1 = v1 - mu, d2 = v2 - mu, d3 = v3 - mu;
    float s2 = warp_sum(d0 * d0 + d1 * d1 + d2 * d2 + d3 * d3);
    if ((tid & 31) == 0) sh[tid >> 5] = s2;
    __syncthreads();
    float tot2 = 0.f;
    #pragma unroll
    for (int i = 0; i < 6; i++) tot2 += sh[i];
    float r = rsqrtf(tot2 * (1.0f / DD) + 1e-5f);

    const float4 wv = *reinterpret_cast<const float4*>(w + tid * 4);
    const float4 bv = *reinterpret_cast<const float4*>(b + tid * 4);
    float o0 = d0 * r * wv.x + bv.x;
    float o1 = d1 * r * wv.y + bv.y;
    float o2 = d2 * r * wv.z + bv.z;
    float o3 = d3 * r * wv.w + bv.w;
    *reinterpret_cast<float4*>(out + (size_t)row * DD + tid * 4) =
        make_float4(o0, o1, o2, o3);
    if (out_r) {
        *reinterpret_cast<float4*>(out_r + (size_t)row * DD + tid * 4) =
            make_float4(to_tf32f(o0), to_tf32f(o1), to_tf32f(o2), to_tf32f(o3));
    }
}

// ---------------------------------------------------------------------------
extern "C" void kernel_launch(void* const* d_in, const int* in_sizes, int n_in,
                              void* d_out, int out_size) {
    const int*   ids      = (const int*)  d_in[0];
    const float* mask     = (const float*)d_in[2];
    const float* tok_emb  = (const float*)d_in[3];
    const float* pos_emb  = (const float*)d_in[4];
    const float* c_attn_w = (const float*)d_in[5];
    const float* c_attn_b = (const float*)d_in[6];
    const float* c_proj_w = (const float*)d_in[7];
    const float* c_proj_b = (const float*)d_in[8];
    const float* ln1_w    = (const float*)d_in[9];
    const float* ln1_b    = (const float*)d_in[10];
    const float* c_fc_w   = (const float*)d_in[11];
    const float* c_fc_b   = (const float*)d_in[12];
    const float* mlp_w    = (const float*)d_in[13];
    const float* mlp_b    = (const float*)d_in[14];
    const float* ln2_w    = (const float*)d_in[15];
    const float* ln2_b    = (const float*)d_in[16];

    float *h, *hr, *n, *nr, *tmp, *attn, *qkv, *fc;
    float *wta, *wtp, *wtf, *wtm;
    cudaGetSymbolAddress((void**)&h,    g_h);
    cudaGetSymbolAddress((void**)&hr,   g_hr);
    cudaGetSymbolAddress((void**)&n,    g_n);
    cudaGetSymbolAddress((void**)&nr,   g_nr);
    cudaGetSymbolAddress((void**)&tmp,  g_tmp);
    cudaGetSymbolAddress((void**)&attn, g_attn);
    cudaGetSymbolAddress((void**)&qkv,  g_qkv);
    cudaGetSymbolAddress((void**)&fc,   g_fc);
    cudaGetSymbolAddress((void**)&wta,  g_wta);
    cudaGetSymbolAddress((void**)&wtp,  g_wtp);
    cudaGetSymbolAddress((void**)&wtf,  g_wtf);
    cudaGetSymbolAddress((void**)&wtm,  g_wtm);

    const int gemmSmem  = 3 * 2 * 128 * 36 * 4;                        // 110592 B
    const int flashSmem = (128 * FS + 4 * 64 * FS + 1024) * 4;         // 108544 B
    static int s_attr_set = 0;
    if (!s_attr_set) {
        cudaFuncSetAttribute(gemm3<0>, cudaFuncAttributeMaxDynamicSharedMemorySize, gemmSmem);
        cudaFuncSetAttribute(gemm3<1>, cudaFuncAttributeMaxDynamicSharedMemorySize, gemmSmem);
        cudaFuncSetAttribute(gemm3<2>, cudaFuncAttributeMaxDynamicSharedMemorySize, gemmSmem);
        cudaFuncSetAttribute(flash_kernel, cudaFuncAttributeMaxDynamicSharedMemorySize, flashSmem);
        s_attr_set = 1;
    }

    detect_kernel<<<1, 1>>>(ids);
    embed_kernel<<<(TOKENS * DD + 255) / 256, 256>>>(ids, tok_emb, pos_emb, h, hr);

    transpose_all<<<T_TOTAL, dim3(32, 8)>>>(c_attn_w, wta, c_proj_w, wtp,
                                            c_fc_w, wtf, mlp_w, wtm);

    for (int i = 0; i < NLAYER; i++) {
        // QKV: hr [4096,768] @ Wt [2304,768]^T  (output tf32-rounded for flash)
        gemm3<2><<<dim3(D3 / 128, TOKENS / 128), 256, gemmSmem>>>(
            hr, wta + (size_t)i * DD * D3, c_attn_b + (size_t)i * D3,
            qkv, D3, DD);

        // fused flash attention -> attn (tf32-rounded)
        flash_kernel<<<dim3(SS / 128, NB * HH), 256, flashSmem>>>(qkv, mask, attn);

        // attn out projection
        gemm3<0><<<dim3(DD / 128, TOKENS / 128), 256, gemmSmem>>>(
            attn, wtp + (size_t)i * DD * DD, c_proj_b + (size_t)i * DD,
            tmp, DD, DD);

        // n = LN(h + attn_proj), nr = rna(n)
        add_ln_kernel<<<TOKENS, 192>>>(h, tmp, ln1_w + i * DD, ln1_b + i * DD, n, nr);

        // fc = rna(gelu(nr @ Wfc + b))
        gemm3<1><<<dim3(D4 / 128, TOKENS / 128), 256, gemmSmem>>>(
            nr, wtf + (size_t)i * DD * D4, c_fc_b + (size_t)i * D4,
            fc, D4, DD);

        // m = fc @ Wmlp + b
        gemm3<0><<<dim3(DD / 128, TOKENS / 128), 256, gemmSmem>>>(
            fc, wtm + (size_t)i * D4 * DD, mlp_b + (size_t)i * DD,
            tmp, DD, D4);

        // h = LN(n + m); last layer -> d_out, no rounded copy
        float* dst = (i == NLAYER - 1) ? (float*)d_out : h;
        float* dstr = (i == NLAYER - 1) ? nullptr : hr;
        add_ln_kernel<<<TOKENS, 192>>>(n, tmp, ln2_w + i * DD, ln2_b + i * DD, dst, dstr);
    }
}

// round 13
// speedup vs baseline: 1.1182x; 1.0849x over previous
#include <cuda_runtime.h>
#include <cuda_bf16.h>
#include <cstdint>

// ---------------------------------------------------------------------------
// GPT-1 forward: B=4, S=1024, D=768, H=12, HD=64, N_LAYER=5
// Round 13: split-K=2 (gridDim.z) for the N=768 GEMMs (proj, MLP-proj);
// 3-input add_ln.  gemm3 core = R9/R12 proven shape.
// ---------------------------------------------------------------------------

#define NB 4
#define SS 1024
#define DD 768
#define HH 12
#define HDD 64
#define NLAYER 5
#define TOKENS (NB * SS)           // 4096
#define D3 (3 * DD)                // 2304
#define D4 (4 * DD)                // 3072

// -------------------- device scratch (no cudaMalloc allowed) ---------------
__device__ __align__(128) float g_h[TOKENS * DD];
__device__ __align__(128) float g_hr[TOKENS * DD];
__device__ __align__(128) float g_n[TOKENS * DD];
__device__ __align__(128) float g_nr[TOKENS * DD];
__device__ __align__(128) float g_tmp[TOKENS * DD];
__device__ __align__(128) float g_tmp2[TOKENS * DD];
__device__ __align__(128) float g_attn[TOKENS * DD];
__device__ __align__(128) float g_qkv[TOKENS * D3];
__device__ __align__(128) float g_fc[TOKENS * D4];
__device__ __align__(128) float g_wta[NLAYER * DD * D3];
__device__ __align__(128) float g_wtp[NLAYER * DD * DD];
__device__ __align__(128) float g_wtf[NLAYER * DD * D4];
__device__ __align__(128) float g_wtm[NLAYER * D4 * DD];
__device__ int g_is_i64;

// -------------------- helpers ----------------------------------------------
__device__ __forceinline__ float warp_sum(float v) {
    #pragma unroll
    for (int o = 16; o; o >>= 1) v += __shfl_xor_sync(0xffffffffu, v, o);
    return v;
}
__device__ __forceinline__ float gelu_f(float x) {
    const float c2 = 1.5957691216057308f;  // 2*sqrt(2/pi)
    float u = c2 * (x + 0.044715f * x * x * x);
    return x / (1.0f + __expf(-u));
}
__device__ __forceinline__ uint32_t to_tf32(float x) {
    uint32_t u;
    asm("cvt.rna.tf32.f32 %0, %1;" : "=r"(u) : "f"(x));
    return u;
}
__device__ __forceinline__ float to_tf32f(float x) {
    return __uint_as_float(to_tf32(x));
}
__device__ __forceinline__ void mma8(float* c, const uint32_t* a, const uint32_t* b) {
    asm volatile(
        "mma.sync.aligned.m16n8k8.row.col.f32.tf32.tf32.f32 "
        "{%0,%1,%2,%3},{%4,%5,%6,%7},{%8,%9},{%0,%1,%2,%3};\n"
        : "+f"(c[0]), "+f"(c[1]), "+f"(c[2]), "+f"(c[3])
        : "r"(a[0]), "r"(a[1]), "r"(a[2]), "r"(a[3]), "r"(b[0]), "r"(b[1]));
}
__device__ __forceinline__ void ldsm4(uint32_t* r, uint32_t addr) {
    asm volatile("ldmatrix.sync.aligned.m8n8.x4.shared.b16 {%0,%1,%2,%3}, [%4];"
                 : "=r"(r[0]), "=r"(r[1]), "=r"(r[2]), "=r"(r[3]) : "r"(addr));
}
__device__ __forceinline__ void cpasync16(uint32_t dst, const float* src) {
    asm volatile("cp.async.cg.shared.global [%0], [%1], 16;" :: "r"(dst), "l"(src));
}

// -------------------- input_ids dtype detection ----------------------------
__global__ void detect_kernel(const int* __restrict__ ids) {
    int any = 0;
    for (int i = 1; i < 64; i += 2) any |= ids[i];
    g_is_i64 = (any == 0) ? 1 : 0;
}

// -------------------- embedding (dual write: fp32 + tf32-rounded) ----------
__global__ void embed_kernel(const int* __restrict__ ids,
                             const float* __restrict__ tok,
                             const float* __restrict__ pos,
                             float* __restrict__ h,
                             float* __restrict__ hr) {
    int i = blockIdx.x * blockDim.x + threadIdx.x;
    if (i >= TOKENS * DD) return;
    int t = i / DD;
    int d = i - t * DD;
    int s = t & (SS - 1);
    int id = g_is_i64 ? ids[2 * t] : ids[t];
    float v = tok[(size_t)id * DD + d] + pos[(size_t)s * DD + d];
    h[i] = v;
    hr[i] = to_tf32f(v);
}

// -------------------- all weight transposes in ONE launch -------------------
#define TA_TILES (NLAYER * (D3 / 32) * (DD / 32))
#define TP_TILES (NLAYER * (DD / 32) * (DD / 32))
#define TF_TILES (NLAYER * (D4 / 32) * (DD / 32))
#define TM_TILES (NLAYER * (DD / 32) * (D4 / 32))
#define T_TOTAL  (TA_TILES + TP_TILES + TF_TILES + TM_TILES)

__global__ void transpose_all(const float* __restrict__ wa, float* __restrict__ ta,
                              const float* __restrict__ wp, float* __restrict__ tp,
                              const float* __restrict__ wf, float* __restrict__ tf,
                              const float* __restrict__ wm, float* __restrict__ tm) {
    __shared__ float t[32][33];
    int bid = blockIdx.x;
    const float* src; float* dst; int K, N;
    if (bid < TA_TILES)            { src = wa; dst = ta; K = DD; N = D3; }
    else if (bid < TA_TILES + TP_TILES) {
        bid -= TA_TILES;            src = wp; dst = tp; K = DD; N = DD; }
    else if (bid < TA_TILES + TP_TILES + TF_TILES) {
        bid -= TA_TILES + TP_TILES; src = wf; dst = tf; K = DD; N = D4; }
    else {
        bid -= TA_TILES + TP_TILES + TF_TILES;
                                    src = wm; dst = tm; K = D4; N = DD; }
    int ntx = N / 32;
    int per = ntx * (K / 32);
    int layer = bid / per;
    int tt = bid - layer * per;
    int n0 = (tt % ntx) * 32;
    int k0 = (tt / ntx) * 32;
    size_t off = (size_t)layer * K * N;

    int tx = threadIdx.x, ty = threadIdx.y;
    #pragma unroll
    for (int i = 0; i < 4; i++)
        t[ty + i * 8][tx] = src[off + (size_t)(k0 + ty + i * 8) * N + n0 + tx];
    __syncthreads();
    #pragma unroll
    for (int i = 0; i < 4; i++)
        dst[off + (size_t)(n0 + ty + i * 8) * K + k0 + tx] =
            to_tf32f(t[tx][ty + i * 8]);
}

// ---------------------------------------------------------------------------
// cp.async 3-stage tf32 GEMM, BK=32, 256 threads = 8 warps of 64x32 (2x4).
// A [M][lda], Bt [N][lda] (both pre-rounded).  blockIdx.z selects the K-half
// (kOff = z*kLen) and the output buffer (C + z*splitStride); bias on z==0.
// MODE 0: +bias.  MODE 1: rna(gelu(+bias)).  MODE 2: rna(+bias).
// ---------------------------------------------------------------------------
template<int MODE>
__global__ __launch_bounds__(256, 2)
void gemm3(const float* __restrict__ A,
           const float* __restrict__ Bt,
           const float* __restrict__ bias,
           float* __restrict__ C, int ldc,
           int lda, int kLen, size_t splitStride) {
    constexpr int BM = 128, BK = 32;
    constexpr int RS = BK + 4;               // 36-word row stride
    constexpr int SW = BM * RS;              // words per operand stage

    extern __shared__ float dyn[];
    float* AsBase = dyn;                      // 3 stages A
    float* BsBase = dyn + 3 * SW;             // 3 stages B

    const int tid  = threadIdx.x;
    const int wid  = tid >> 5;
    const int lane = tid & 31;
    const int g    = lane >> 2;
    const int tg   = lane & 3;
    const int warpM = (wid >> 2) * 64;
    const int warpN = (wid & 3) * 32;
    const int rowBase = blockIdx.y * BM;
    const int colBase = blockIdx.x * BM;
    const int z = blockIdx.z;
    const int kOff = z * kLen;
    C += (size_t)z * splitStride;

    const uint32_t aSm = (uint32_t)__cvta_generic_to_shared(AsBase);
    const uint32_t bSm = (uint32_t)__cvta_generic_to_shared(BsBase);
    const uint32_t aLaneOff = ((lane & 15) * RS + ((lane & 16) ? 4 : 0)) * 4;
    const uint32_t bLaneOff = ((((lane & 7) | ((lane & 16) >> 1))) * RS +
                               ((lane & 8) ? 4 : 0)) * 4;

    const int r  = tid >> 3;        // 0..31 (+32/64/96 for later batches)
    const int kq = tid & 7;

    float acc[4][4][4];
    #pragma unroll
    for (int i = 0; i < 4; i++)
        #pragma unroll
        for (int j = 0; j < 4; j++)
            #pragma unroll
            for (int q = 0; q < 4; q++) acc[i][j][q] = 0.0f;

    auto stage = [&](int kt, int buf) {
        int k0 = kOff + kt * BK;
        uint32_t aB = aSm + buf * SW * 4;
        uint32_t bB = bSm + buf * SW * 4;
        #pragma unroll
        for (int it = 0; it < 4; it++) {
            int rr = r + it * 32;
            cpasync16(aB + (rr * RS + kq * 4) * 4,
                      A + (size_t)(rowBase + rr) * lda + k0 + kq * 4);
        }
        #pragma unroll
        for (int it = 0; it < 4; it++) {
            int nn = r + it * 32;
            cpasync16(bB + (nn * RS + kq * 4) * 4,
                      Bt + (size_t)(colBase + nn) * lda + k0 + kq * 4);
        }
        asm volatile("cp.async.commit_group;");
    };

    const int KT = kLen / BK;
    stage(0, 0);
    stage(1, 1);

    for (int kt = 0; kt < KT; kt++) {
        if (kt == KT - 1)
            asm volatile("cp.async.wait_group 0;");
        else
            asm volatile("cp.async.wait_group 1;");
        __syncthreads();
        if (kt + 2 < KT) stage(kt + 2, (kt + 2) % 3);

        int buf = kt % 3;
        uint32_t aBase = aSm + buf * SW * 4 + aLaneOff + (warpM * RS) * 4;
        uint32_t bBase = bSm + buf * SW * 4 + bLaneOff + (warpN * RS) * 4;
        #pragma unroll
        for (int kk = 0; kk < BK; kk += 8) {
            uint32_t af[4][4];
            #pragma unroll
            for (int i = 0; i < 4; i++)
                ldsm4(af[i], aBase + kk * 4 + i * (16 * RS * 4));
            uint32_t bf[4][2];
            {
                uint32_t t[4];
                ldsm4(t, bBase + kk * 4);
                bf[0][0] = t[0]; bf[0][1] = t[1];
                bf[1][0] = t[2]; bf[1][1] = t[3];
                ldsm4(t, bBase + kk * 4 + 16 * RS * 4);
                bf[2][0] = t[0]; bf[2][1] = t[1];
                bf[3][0] = t[2]; bf[3][1] = t[3];
            }
            #pragma unroll
            for (int i = 0; i < 4; i++)
                #pragma unroll
                for (int j = 0; j < 4; j++)
                    mma8(acc[i][j], af[i], bf[j]);
        }
    }

    const bool addBias = (z == 0);
    #pragma unroll
    for (int i = 0; i < 4; i++) {
        int r0 = rowBase + warpM + i * 16 + g;
        int r1 = r0 + 8;
        #pragma unroll
        for (int j = 0; j < 4; j++) {
            int c = colBase + warpN + j * 8 + tg * 2;
            float bb0 = addBias ? bias[c]     : 0.0f;
            float bb1 = addBias ? bias[c + 1] : 0.0f;
            float v0 = acc[i][j][0] + bb0, v1 = acc[i][j][1] + bb1;
            float v2 = acc[i][j][2] + bb0, v3 = acc[i][j][3] + bb1;
            if (MODE == 1) {
                v0 = to_tf32f(gelu_f(v0)); v1 = to_tf32f(gelu_f(v1));
                v2 = to_tf32f(gelu_f(v2)); v3 = to_tf32f(gelu_f(v3));
            }
            if (MODE == 2) {
                v0 = to_tf32f(v0); v1 = to_tf32f(v1);
                v2 = to_tf32f(v2); v3 = to_tf32f(v3);
            }
            *reinterpret_cast<float2*>(C + (size_t)r0 * ldc + c) = make_float2(v0, v1);
            *reinterpret_cast<float2*>(C + (size_t)r1 * ldc + c) = make_float2(v2, v3);
        }
    }
}

// ---------------------------------------------------------------------------
// Fused flash attention: 128 q-rows/CTA, 8 warps (16 rows each).
// Inputs (qkv) pre-rounded by QKV GEMM epilogue.  K/V double-buffered via
// cp.async.  q-tiles processed in reverse block order (heavy first).
// ---------------------------------------------------------------------------
#define FS 68

__global__ __launch_bounds__(256)
void flash_kernel(const float* __restrict__ qkv,
                  const float* __restrict__ mask,
                  float* __restrict__ attn) {
    extern __shared__ float sm[];
    float* Qs  = sm;                      // [128 m][68 d]
    float* Ks  = Qs + 128 * FS;           // [2][64 t][68 d]
    float* Vs  = Ks + 2 * 64 * FS;        // [2][64 t][68 d]
    float* Ems = Vs + 2 * 64 * FS;        // [1024]

    const int tid  = threadIdx.x;
    const int wid  = tid >> 5;
    const int lane = tid & 31;
    const int g    = lane >> 2;
    const int tg   = lane & 3;
    const int qi = gridDim.x - 1 - blockIdx.x;   // heavy tiles first
    const int qBase = qi * 128;
    const int bh = blockIdx.y;
    const int b = bh / HH, h = bh - b * HH;

    const float* Qg = qkv + (size_t)b * SS * D3 + h * HDD;
    const float* Kg = Qg + DD;
    const float* Vg = Qg + 2 * DD;

    const uint32_t qSm = (uint32_t)__cvta_generic_to_shared(Qs);
    const uint32_t kSm = (uint32_t)__cvta_generic_to_shared(Ks);
    const uint32_t vSm = (uint32_t)__cvta_generic_to_shared(Vs);

    #pragma unroll
    for (int i = 0; i < 8; i++) {
        int idx = i * 256 + tid;
        int r = idx >> 4, dq = idx & 15;
        cpasync16(qSm + (r * FS + dq * 4) * 4,
                  Qg + (size_t)(qBase + r) * D3 + dq * 4);
    }
    auto stageKV = [&](int kb, int buf) {
        uint32_t kD = kSm + buf * 64 * FS * 4;
        uint32_t vD = vSm + buf * 64 * FS * 4;
        const float* Kt = Kg + (size_t)(kb * 64) * D3;
        const float* Vt = Vg + (size_t)(kb * 64) * D3;
        #pragma unroll
        for (int i = 0; i < 4; i++) {
            int idx = i * 256 + tid;
            int kt = idx >> 4, dq = idx & 15;
            cpasync16(kD + (kt * FS + dq * 4) * 4, Kt + (size_t)kt * D3 + dq * 4);
            cpasync16(vD + (kt * FS + dq * 4) * 4, Vt + (size_t)kt * D3 + dq * 4);
        }
        asm volatile("cp.async.commit_group;");
    };
    stageKV(0, 0);

    #pragma unroll
    for (int i = 0; i < 4; i++) {
        int idx = i * 256 + tid;
        Ems[idx] = (1.0f - mask[b * SS + idx]) * (-3.402823466e38f);
    }

    float o[8][4];
    #pragma unroll
    for (int j = 0; j < 8; j++)
        #pragma unroll
        for (int q = 0; q < 4; q++) o[j][q] = 0.0f;
    float mrow0 = -1e30f, mrow1 = -1e30f;
    float lrow0 = 0.f, lrow1 = 0.f;

    const int row0 = qBase + wid * 16 + g;
    const int row1 = row0 + 8;
    const int srcA = (lane & 28) | (tg >> 1);
    const int srcB = srcA | 2;
    const int e1   = tg & 1;

    const uint32_t aOff = ((wid * 16 + (lane & 15)) * FS + ((lane & 16) ? 4 : 0)) * 4;
    const uint32_t bOff = ((((lane & 7) | ((lane & 16) >> 1))) * FS +
                           ((lane & 8) ? 4 : 0)) * 4;

    const int nkb = qi * 2 + 2;
    for (int kb = 0; kb < nkb; kb++) {
        asm volatile("cp.async.wait_group 0;");
        __syncthreads();
        if (kb + 1 < nkb) stageKV(kb + 1, (kb + 1) & 1);

        const uint32_t kBuf = kSm + (kb & 1) * 64 * FS * 4;
        const float*  VsB  = Vs + (kb & 1) * 64 * FS;

        float s[8][4];
        #pragma unroll
        for (int j = 0; j < 8; j++)
            #pragma unroll
            for (int q = 0; q < 4; q++) s[j][q] = 0.0f;

        #pragma unroll
        for (int kk = 0; kk < 8; kk++) {
            uint32_t af[4];
            ldsm4(af, qSm + aOff + kk * 8 * 4);
            uint32_t bf[8][2];
            #pragma unroll
            for (int m = 0; m < 4; m++) {
                uint32_t t4[4];
                ldsm4(t4, kBuf + bOff + (m * 16 * FS + kk * 8) * 4);
                bf[2 * m][0] = t4[0]; bf[2 * m][1] = t4[1];
                bf[2 * m + 1][0] = t4[2]; bf[2 * m + 1][1] = t4[3];
            }
            #pragma unroll
            for (int j = 0; j < 8; j++)
                mma8(s[j], af, bf[j]);
        }

        float mx0 = -1e30f, mx1 = -1e30f;
        #pragma unroll
        for (int j = 0; j < 8; j++) {
            int c0 = kb * 64 + j * 8 + tg * 2;
            float em0 = Ems[c0];
            float em1 = Ems[c0 + 1];
            float v0 = s[j][0] * 0.125f;
            float v1 = s[j][1] * 0.125f;
            float v2 = s[j][2] * 0.125f;
            float v3 = s[j][3] * 0.125f;
            if (c0 > row0)     v0 = -1e4f;
            if (c0 + 1 > row0) v1 = -1e4f;
            if (c0 > row1)     v2 = -1e4f;
            if (c0 + 1 > row1) v3 = -1e4f;
            v0 += em0; v1 += em1; v2 += em0; v3 += em1;
            s[j][0] = v0; s[j][1] = v1; s[j][2] = v2; s[j][3] = v3;
            mx0 = fmaxf(mx0, fmaxf(v0, v1));
            mx1 = fmaxf(mx1, fmaxf(v2, v3));
        }
        mx0 = fmaxf(mx0, __shfl_xor_sync(0xffffffffu, mx0, 1));
        mx0 = fmaxf(mx0, __shfl_xor_sync(0xffffffffu, mx0, 2));
        mx1 = fmaxf(mx1, __shfl_xor_sync(0xffffffffu, mx1, 1));
        mx1 = fmaxf(mx1, __shfl_xor_sync(0xffffffffu, mx1, 2));

        float mn0 = fmaxf(mrow0, mx0);
        float mn1 = fmaxf(mrow1, mx1);
        float al0 = __expf(mrow0 - mn0);
        float al1 = __expf(mrow1 - mn1);
        mrow0 = mn0; mrow1 = mn1;

        float sum0 = 0.f, sum1 = 0.f;
        #pragma unroll
        for (int j = 0; j < 8; j++) {
            float p0 = __expf(s[j][0] - mn0);
            float p1 = __expf(s[j][1] - mn0);
            float p2 = __expf(s[j][2] - mn1);
            float p3 = __expf(s[j][3] - mn1);
            s[j][0] = p0; s[j][1] = p1; s[j][2] = p2; s[j][3] = p3;
            sum0 += p0 + p1; sum1 += p2 + p3;
        }
        sum0 += __shfl_xor_sync(0xffffffffu, sum0, 1);
        sum0 += __shfl_xor_sync(0xffffffffu, sum0, 2);
        sum1 += __shfl_xor_sync(0xffffffffu, sum1, 1);
        sum1 += __shfl_xor_sync(0xffffffffu, sum1, 2);
        lrow0 = lrow0 * al0 + sum0;
        lrow1 = lrow1 * al1 + sum1;

        #pragma unroll
        for (int jo = 0; jo < 8; jo++) {
            o[jo][0] *= al0; o[jo][1] *= al0;
            o[jo][2] *= al1; o[jo][3] *= al1;
        }

        #pragma unroll
        for (int j = 0; j < 8; j++) {
            float x0A = __shfl_sync(0xffffffffu, s[j][0], srcA);
            float x1A = __shfl_sync(0xffffffffu, s[j][1], srcA);
            float x0B = __shfl_sync(0xffffffffu, s[j][0], srcB);
            float x1B = __shfl_sync(0xffffffffu, s[j][1], srcB);
            float y0A = __shfl_sync(0xffffffffu, s[j][2], srcA);
            float y1A = __shfl_sync(0xffffffffu, s[j][3], srcA);
            float y0B = __shfl_sync(0xffffffffu, s[j][2], srcB);
            float y1B = __shfl_sync(0xffffffffu, s[j][3], srcB);
            uint32_t pa[4];
            pa[0] = to_tf32(e1 ? x1A : x0A);
            pa[1] = to_tf32(e1 ? y1A : y0A);
            pa[2] = to_tf32(e1 ? x1B : x0B);
            pa[3] = to_tf32(e1 ? y1B : y0B);
            #pragma unroll
            for (int jo = 0; jo < 8; jo++) {
                uint32_t bf[2];
                bf[0] = __float_as_uint(VsB[(j * 8 + tg) * FS + jo * 8 + g]);
                bf[1] = __float_as_uint(VsB[(j * 8 + tg + 4) * FS + jo * 8 + g]);
                mma8(o[jo], pa, bf);
            }
        }
    }

    float inv0 = 1.0f / lrow0;
    float inv1 = 1.0f / lrow1;
    #pragma unroll
    for (int jo = 0; jo < 8; jo++) {
        int col = h * HDD + jo * 8 + tg * 2;
        *reinterpret_cast<float2*>(attn + (size_t)(b * SS + row0) * DD + col) =
            make_float2(to_tf32f(o[jo][0] * inv0), to_tf32f(o[jo][1] * inv0));
        *reinterpret_cast<float2*>(attn + (size_t)(b * SS + row1) * DD + col) =
            make_float2(to_tf32f(o[jo][2] * inv1), to_tf32f(o[jo][3] * inv1));
    }
}

// ------------- fused residual-add + LayerNorm (3 inputs, float4) -----------
__global__ __launch_bounds__(192)
void add_ln_kernel(const float* __restrict__ x,
                   const float* __restrict__ y,
                   const float* __restrict__ y2,
                   const float* __restrict__ w,
                   const float* __restrict__ b,
                   float* __restrict__ out,
                   float* __restrict__ out_r) {
    int row = blockIdx.x;
    int tid = threadIdx.x;   // 0..191, one float4 each (192*4 = 768)
    const float4 xv = *reinterpret_cast<const float4*>(x + (size_t)row * DD + tid * 4);
    const float4 yv = *reinterpret_cast<const float4*>(y + (size_t)row * DD + tid * 4);
    float v0 = xv.x + yv.x, v1 = xv.y + yv.y, v2 = xv.z + yv.z, v3 = xv.w + yv.w;
    if (y2) {
        const float4 zv = *reinterpret_cast<const float4*>(y2 + (size_t)row * DD + tid * 4);
        v0 += zv.x; v1 += zv.y; v2 += zv.z; v3 += zv.w;
    }

    __shared__ float sh[6];
    float s = warp_sum(v0 + v1 + v2 + v3);
    if ((tid & 31) == 0) sh[tid >> 5] = s;
    __syncthreads();
    float tot = 0.f;
    #pragma unroll
    for (int i = 0; i < 6; i++) tot += sh[i];
    float mu = tot * (1.0f / DD);
    __syncthreads();

    float d0 = v0 - mu, d1 = v1 - mu, d2 = v2 - mu, d3 = v3 - mu;
    float s2 = warp_sum(d0 * d0 + d1 * d1 + d2 * d2 + d3 * d3);
    if ((tid & 31) == 0) sh[tid >> 5] = s2;
    __syncthreads();
    float tot2 = 0.f;
    #pragma unroll
    for (int i = 0; i < 6; i++) tot2 += sh[i];
    float r = rsqrtf(tot2 * (1.0f / DD) + 1e-5f);

    const float4 wv = *reinterpret_cast<const float4*>(w + tid * 4);
    const float4 bv = *reinterpret_cast<const float4*>(b + tid * 4);
    float o0 = d0 * r * wv.x + bv.x;
    float o1 = d1 * r * wv.y + bv.y;
    float o2 = d2 * r * wv.z + bv.z;
    float o3 = d3 * r * wv.w + bv.w;
    *reinterpret_cast<float4*>(out + (size_t)row * DD + tid * 4) =
        make_float4(o0, o1, o2, o3);
    if (out_r) {
        *reinterpret_cast<float4*>(out_r + (size_t)row * DD + tid * 4) =
            make_float4(to_tf32f(o0), to_tf32f(o1), to_tf32f(o2), to_tf32f(o3));
    }
}

// ---------------------------------------------------------------------------
extern "C" void kernel_launch(void* const* d_in, const int* in_sizes, int n_in,
                              void* d_out, int out_size) {
    const int*   ids      = (const int*)  d_in[0];
    const float* mask     = (const float*)d_in[2];
    const float* tok_emb  = (const float*)d_in[3];
    const float* pos_emb  = (const float*)d_in[4];
    const float* c_attn_w = (const float*)d_in[5];
    const float* c_attn_b = (const float*)d_in[6];
    const float* c_proj_w = (const float*)d_in[7];
    const float* c_proj_b = (const float*)d_in[8];
    const float* ln1_w    = (const float*)d_in[9];
    const float* ln1_b    = (const float*)d_in[10];
    const float* c_fc_w   = (const float*)d_in[11];
    const float* c_fc_b   = (const float*)d_in[12];
    const float* mlp_w    = (const float*)d_in[13];
    const float* mlp_b    = (const float*)d_in[14];
    const float* ln2_w    = (const float*)d_in[15];
    const float* ln2_b    = (const float*)d_in[16];

    float *h, *hr, *n, *nr, *tmp, *tmp2, *attn, *qkv, *fc;
    float *wta, *wtp, *wtf, *wtm;
    cudaGetSymbolAddress((void**)&h,    g_h);
    cudaGetSymbolAddress((void**)&hr,   g_hr);
    cudaGetSymbolAddress((void**)&n,    g_n);
    cudaGetSymbolAddress((void**)&nr,   g_nr);
    cudaGetSymbolAddress((void**)&tmp,  g_tmp);
    cudaGetSymbolAddress((void**)&tmp2, g_tmp2);
    cudaGetSymbolAddress((void**)&attn, g_attn);
    cudaGetSymbolAddress((void**)&qkv,  g_qkv);
    cudaGetSymbolAddress((void**)&fc,   g_fc);
    cudaGetSymbolAddress((void**)&wta,  g_wta);
    cudaGetSymbolAddress((void**)&wtp,  g_wtp);
    cudaGetSymbolAddress((void**)&wtf,  g_wtf);
    cudaGetSymbolAddress((void**)&wtm,  g_wtm);

    const size_t SPLIT = (size_t)TOKENS * DD;  // tmp2 - tmp handled via ptr math
    const int gemmSmem  = 3 * 2 * 128 * 36 * 4;                        // 110592 B
    const int flashSmem = (128 * FS + 4 * 64 * FS + 1024) * 4;         // 108544 B
    static int s_attr_set = 0;
    if (!s_attr_set) {
        cudaFuncSetAttribute(gemm3<0>, cudaFuncAttributeMaxDynamicSharedMemorySize, gemmSmem);
        cudaFuncSetAttribute(gemm3<1>, cudaFuncAttributeMaxDynamicSharedMemorySize, gemmSmem);
        cudaFuncSetAttribute(gemm3<2>, cudaFuncAttributeMaxDynamicSharedMemorySize, gemmSmem);
        cudaFuncSetAttribute(flash_kernel, cudaFuncAttributeMaxDynamicSharedMemorySize, flashSmem);
        s_attr_set = 1;
    }

    detect_kernel<<<1, 1>>>(ids);
    embed_kernel<<<(TOKENS * DD + 255) / 256, 256>>>(ids, tok_emb, pos_emb, h, hr);

    transpose_all<<<T_TOTAL, dim3(32, 8)>>>(c_attn_w, wta, c_proj_w, wtp,
                                            c_fc_w, wtf, mlp_w, wtm);

    // NOTE: tmp2 must sit exactly SPLIT elements after tmp for the z-split
    // epilogue (C + z*splitStride).  g_tmp and g_tmp2 are separate symbols,
    // so pass the actual delta instead of assuming adjacency.
    const size_t tmpDelta = (size_t)(tmp2 - tmp);

    for (int i = 0; i < NLAYER; i++) {
        // QKV: hr [4096,768] @ Wt [2304,768]^T  (output tf32-rounded)
        gemm3<2><<<dim3(D3 / 128, TOKENS / 128, 1), 256, gemmSmem>>>(
            hr, wta + (size_t)i * DD * D3, c_attn_b + (size_t)i * D3,
            qkv, D3, DD, DD, 0);

        // fused flash attention -> attn (tf32-rounded)
        flash_kernel<<<dim3(SS / 128, NB * HH), 256, flashSmem>>>(qkv, mask, attn);

        // attn out projection, split-K=2 over z: tmp (z=0,+bias) & tmp2 (z=1)
        gemm3<0><<<dim3(DD / 128, TOKENS / 128, 2), 256, gemmSmem>>>(
            attn, wtp + (size_t)i * DD * DD, c_proj_b + (size_t)i * DD,
            tmp, DD, DD, DD / 2, tmpDelta);

        // n = LN(h + tmp + tmp2), nr = rna(n)
        add_ln_kernel<<<TOKENS, 192>>>(h, tmp, tmp2,
                                       ln1_w + i * DD, ln1_b + i * DD, n, nr);

        // fc = rna(gelu(nr @ Wfc + b))
        gemm3<1><<<dim3(D4 / 128, TOKENS / 128, 1), 256, gemmSmem>>>(
            nr, wtf + (size_t)i * DD * D4, c_fc_b + (size_t)i * D4,
            fc, D4, DD, DD, 0);

        // m = fc @ Wmlp + b, split-K=2 over z
        gemm3<0><<<dim3(DD / 128, TOKENS / 128, 2), 256, gemmSmem>>>(
            fc, wtm + (size_t)i * D4 * DD, mlp_b + (size_t)i * DD,
            tmp, DD, D4, D4 / 2, tmpDelta);

        // h = LN(n + tmp + tmp2); last layer -> d_out
        float* dst = (i == NLAYER - 1) ? (float*)d_out : h;
        float* dstr = (i == NLAYER - 1) ? nullptr : hr;
        add_ln_kernel<<<TOKENS, 192>>>(n, tmp, tmp2,
                                       ln2_w + i * DD, ln2_b + i * DD, dst, dstr);
    }
}